// round 3
// baseline (speedup 1.0000x reference)
#include <cuda_runtime.h>
#include <cstdint>

#define N     8192
#define K1    31
#define CAP   256      // per-line candidate capacity (expected ~88, max seen ~135)
#define PIVOT 2.3f     // P(z>2.3)=0.0107 -> E[cand]=88 per line

__device__ unsigned long long g_rowcand[(size_t)N * CAP]; // 16 MB
__device__ unsigned long long g_colcand[(size_t)N * CAP]; // 16 MB
__device__ int                g_rowcnt[N];
__device__ int                g_colcnt[N];
__device__ unsigned long long g_rowth[N];

// Monotone map float -> uint32 (larger float => larger key)
__device__ __forceinline__ unsigned int fkey(float x) {
    unsigned int u = __float_as_uint(x);
    return (u & 0x80000000u) ? ~u : (u | 0x80000000u);
}
__device__ __forceinline__ float inv_fkey(unsigned int k) {
    unsigned int u = (k & 0x80000000u) ? (k ^ 0x80000000u) : ~k;
    return __uint_as_float(u);
}
// Composite key: value-major, lower index wins ties (stable top_k semantics)
__device__ __forceinline__ unsigned long long ckey(float x, int idx) {
    return ((unsigned long long)fkey(x) << 32) | (unsigned int)(N - 1 - idx);
}

__global__ void zero_kernel() {
    int t = blockIdx.x * blockDim.x + threadIdx.x;
    if (t < N) { g_rowcnt[t] = 0; g_colcnt[t] = 0; }
}

// --- generic fallback: K1-th largest composite key of a full line (exact) ---
template <bool ROW>
__device__ unsigned long long fallback_select(const float* __restrict__ A, int line) {
    __shared__ unsigned long long red[256];
    unsigned long long prev = 0xFFFFFFFFFFFFFFFFull;
    for (int it = 0; it < K1; it++) {
        unsigned long long best = 0;
        for (int t = threadIdx.x; t < N; t += 256) {
            float x = ROW ? A[(size_t)line * N + t] : A[(size_t)t * N + line];
            unsigned long long k = ckey(x, t);
            if (k < prev && k > best) best = k;
        }
        red[threadIdx.x] = best;
        __syncthreads();
        for (int s = 128; s > 0; s >>= 1) {
            if (threadIdx.x < s) {
                unsigned long long o = red[threadIdx.x + s];
                if (o > red[threadIdx.x]) red[threadIdx.x] = o;
            }
            __syncthreads();
        }
        prev = red[0];
        __syncthreads();
    }
    return prev;
}

// Phase 1: flat streaming pass. Reads A (256MB), writes zeros to out (256MB),
// pushes candidates (> PIVOT) into per-row and per-column global lists.
__global__ __launch_bounds__(256) void stream_kernel(const float* __restrict__ A,
                                                     float* __restrict__ out) {
    const size_t g0 = ((size_t)blockIdx.x * 256 + threadIdx.x) * 2; // float4 idx
    const float4* Ap = (const float4*)A;
    float4* Op = (float4*)out;
    // front-batched independent loads (MLP=2)
    float4 v0 = __ldcs(&Ap[g0]);
    float4 v1 = __ldcs(&Ap[g0 + 1]);
    const float4 zz = {0.0f, 0.0f, 0.0f, 0.0f};
    __stcs(&Op[g0], zz);
    __stcs(&Op[g0 + 1], zz);

    const int i  = (int)(g0 >> 11);            // 2048 float4 per row; both in row i
    const int j0 = (int)(g0 & 2047) * 4;
    float xs[8] = {v0.x, v0.y, v0.z, v0.w, v1.x, v1.y, v1.z, v1.w};
#pragma unroll
    for (int c = 0; c < 8; c++) {
        float x = xs[c];
        if (x > PIVOT) {
            int j = j0 + c;
            int rs = atomicAdd(&g_rowcnt[i], 1);
            if (rs < CAP) g_rowcand[(size_t)i * CAP + rs] = ckey(x, j);
            int cs = atomicAdd(&g_colcnt[j], 1);
            if (cs < CAP) g_colcand[(size_t)j * CAP + cs] = ckey(x, i);
        }
    }
}

// Phase 2a: row thresholds from candidate lists (rank-by-counting).
__global__ __launch_bounds__(256) void rowth_kernel(const float* __restrict__ A) {
    const int i = blockIdx.x;
    const int c = g_rowcnt[i];
    __shared__ unsigned long long cand[CAP];
    if (c >= K1 && c <= CAP) {
        for (int t = threadIdx.x; t < c; t += 256)
            cand[t] = g_rowcand[(size_t)i * CAP + t];
        __syncthreads();
        for (int t = threadIdx.x; t < c; t += 256) {
            unsigned long long kt = cand[t];
            int r = 0;
            for (int m = 0; m < c; m++) r += (cand[m] > kt);
            if (r == K1 - 1) g_rowth[i] = kt;
        }
    } else {
        unsigned long long th = fallback_select<true>(A, i);
        if (threadIdx.x == 0) g_rowth[i] = th;
    }
}

// Phase 2b: column thresholds + fused scatter of survivors.
// Every entry passing both thresholds has value > PIVOT, so it is in the
// column candidate list (unless that list overflowed -> rescan column).
__global__ __launch_bounds__(256) void colth_scatter_kernel(const float* __restrict__ A,
                                                            float* __restrict__ out) {
    const int j = blockIdx.x;
    const int c = g_colcnt[j];
    __shared__ unsigned long long cand[CAP];
    __shared__ unsigned long long sh_cth;

    if (c >= K1 && c <= CAP) {
        for (int t = threadIdx.x; t < c; t += 256)
            cand[t] = g_colcand[(size_t)j * CAP + t];
        __syncthreads();
        for (int t = threadIdx.x; t < c; t += 256) {
            unsigned long long kt = cand[t];
            int r = 0;
            for (int m = 0; m < c; m++) r += (cand[m] > kt);
            if (r == K1 - 1) sh_cth = kt;
        }
        __syncthreads();
        const unsigned long long cth = sh_cth;
        // scatter survivors of column j
        for (int t = threadIdx.x; t < c; t += 256) {
            unsigned long long k = cand[t];
            if (k < cth) continue;
            int i = N - 1 - (int)(unsigned int)(k & 0xFFFFFFFFu);
            if (i == j) continue;
            float x = inv_fkey((unsigned int)(k >> 32));
            if (ckey(x, j) >= g_rowth[i])
                out[(size_t)i * N + j] = x;
        }
    } else {
        // exact threshold, then full-column rescan for coverage
        unsigned long long cth = fallback_select<false>(A, j);
        for (int i = threadIdx.x; i < N; i += 256) {
            if (i == j) continue;
            float x = A[(size_t)i * N + j];
            unsigned long long k = ckey(x, i);
            if (k >= cth && ckey(x, j) >= g_rowth[i])
                out[(size_t)i * N + j] = x;
        }
    }
}

extern "C" void kernel_launch(void* const* d_in, const int* in_sizes, int n_in,
                              void* d_out, int out_size) {
    const float* A = (const float*)d_in[0];
    float* out = (float*)d_out;
    zero_kernel<<<(N + 255) / 256, 256>>>();
    stream_kernel<<<(size_t)N * (N / 4) / (256 * 2), 256>>>(A, out);
    rowth_kernel<<<N, 256>>>(A);
    colth_scatter_kernel<<<N, 256>>>(A, out);
}

// round 4
// speedup vs baseline: 1.1003x; 1.1003x over previous
#include <cuda_runtime.h>
#include <cstdint>

#define N     8192
#define K1    31
#define CAP   256      // per-line candidate capacity (expected ~88, max seen ~135)
#define PIVOT 2.3f     // P(z>2.3)=0.0107 -> E[cand]=88 per line
#define NF4   (N * (size_t)N / 4)   // float4 count
#define HALF  (NF4 / 2)

__device__ unsigned long long g_rowcand[(size_t)N * CAP]; // 16 MB
__device__ unsigned long long g_colcand[(size_t)N * CAP]; // 16 MB
__device__ int                g_rowcnt[N];
__device__ int                g_colcnt[N];
__device__ unsigned long long g_rowth[N];

// Monotone map float -> uint32 (larger float => larger key)
__device__ __forceinline__ unsigned int fkey(float x) {
    unsigned int u = __float_as_uint(x);
    return (u & 0x80000000u) ? ~u : (u | 0x80000000u);
}
__device__ __forceinline__ float inv_fkey(unsigned int k) {
    unsigned int u = (k & 0x80000000u) ? (k ^ 0x80000000u) : ~k;
    return __uint_as_float(u);
}
// Composite key: value-major, lower index wins ties (stable top_k semantics)
__device__ __forceinline__ unsigned long long ckey(float x, int idx) {
    return ((unsigned long long)fkey(x) << 32) | (unsigned int)(N - 1 - idx);
}

__global__ void zero_kernel() {
    int t = blockIdx.x * blockDim.x + threadIdx.x;
    if (t < N) { g_rowcnt[t] = 0; g_colcnt[t] = 0; }
}

// --- generic fallback: K1-th largest composite key of a full line (exact) ---
template <bool ROW, int BT>
__device__ unsigned long long fallback_select(const float* __restrict__ A, int line) {
    __shared__ unsigned long long red[BT];
    unsigned long long prev = 0xFFFFFFFFFFFFFFFFull;
    for (int it = 0; it < K1; it++) {
        unsigned long long best = 0;
        for (int t = threadIdx.x; t < N; t += BT) {
            float x = ROW ? A[(size_t)line * N + t] : A[(size_t)t * N + line];
            unsigned long long k = ckey(x, t);
            if (k < prev && k > best) best = k;
        }
        red[threadIdx.x] = best;
        __syncthreads();
        for (int s = BT / 2; s > 0; s >>= 1) {
            if (threadIdx.x < s) {
                unsigned long long o = red[threadIdx.x + s];
                if (o > red[threadIdx.x]) red[threadIdx.x] = o;
            }
            __syncthreads();
        }
        prev = red[0];
        __syncthreads();
    }
    return prev;
}

__device__ __forceinline__ void push_cand(float xs[4], int i, int j0) {
#pragma unroll
    for (int c = 0; c < 4; c++) {
        float x = xs[c];
        if (x > PIVOT) {
            int j = j0 + c;
            int rs = atomicAdd(&g_rowcnt[i], 1);
            if (rs < CAP) g_rowcand[(size_t)i * CAP + rs] = ckey(x, j);
            int cs = atomicAdd(&g_colcnt[j], 1);
            if (cs < CAP) g_colcand[(size_t)j * CAP + cs] = ckey(x, i);
        }
    }
}

// Phase 1: flat streaming pass, fully coalesced, MLP=2 via two grid halves.
// Reads A (256MB), writes zeros to out (256MB), pushes candidates.
__global__ __launch_bounds__(256) void stream_kernel(const float* __restrict__ A,
                                                     float* __restrict__ out) {
    const size_t g0 = (size_t)blockIdx.x * 256 + threadIdx.x;  // float4 index, half 0
    const size_t g1 = g0 + HALF;                               // half 1
    const float4* Ap = (const float4*)A;
    float4* Op = (float4*)out;
    // two independent, coalesced, front-batched loads
    float4 v0 = __ldcs(&Ap[g0]);
    float4 v1 = __ldcs(&Ap[g1]);
    const float4 zz = {0.0f, 0.0f, 0.0f, 0.0f};
    __stcs(&Op[g0], zz);
    __stcs(&Op[g1], zz);

    float xs0[4] = {v0.x, v0.y, v0.z, v0.w};
    float xs1[4] = {v1.x, v1.y, v1.z, v1.w};
    push_cand(xs0, (int)(g0 >> 11), (int)(g0 & 2047) * 4);
    push_cand(xs1, (int)(g1 >> 11), (int)(g1 & 2047) * 4);
}

// Phase 2a: row thresholds from candidate lists (rank-by-counting).
__global__ __launch_bounds__(128) void rowth_kernel(const float* __restrict__ A) {
    const int i = blockIdx.x;
    const int c = g_rowcnt[i];
    __shared__ unsigned long long cand[CAP];
    if (c >= K1 && c <= CAP) {
        for (int t = threadIdx.x; t < c; t += 128)
            cand[t] = g_rowcand[(size_t)i * CAP + t];
        __syncthreads();
        for (int t = threadIdx.x; t < c; t += 128) {
            unsigned long long kt = cand[t];
            int r = 0;
            for (int m = 0; m < c; m++) r += (cand[m] > kt);
            if (r == K1 - 1) g_rowth[i] = kt;
        }
    } else {
        unsigned long long th = fallback_select<true, 128>(A, i);
        if (threadIdx.x == 0) g_rowth[i] = th;
    }
}

// Phase 2b: column thresholds + fused scatter of survivors.
// Every entry passing both thresholds has value > PIVOT, so it is in the
// column candidate list (unless that list overflowed -> rescan column).
__global__ __launch_bounds__(128) void colth_scatter_kernel(const float* __restrict__ A,
                                                            float* __restrict__ out) {
    const int j = blockIdx.x;
    const int c = g_colcnt[j];
    __shared__ unsigned long long cand[CAP];
    __shared__ unsigned long long sh_cth;

    if (c >= K1 && c <= CAP) {
        for (int t = threadIdx.x; t < c; t += 128)
            cand[t] = g_colcand[(size_t)j * CAP + t];
        __syncthreads();
        for (int t = threadIdx.x; t < c; t += 128) {
            unsigned long long kt = cand[t];
            int r = 0;
            for (int m = 0; m < c; m++) r += (cand[m] > kt);
            if (r == K1 - 1) sh_cth = kt;
        }
        __syncthreads();
        const unsigned long long cth = sh_cth;
        // scatter survivors of column j
        for (int t = threadIdx.x; t < c; t += 128) {
            unsigned long long k = cand[t];
            if (k < cth) continue;
            int i = N - 1 - (int)(unsigned int)(k & 0xFFFFFFFFu);
            if (i == j) continue;
            float x = inv_fkey((unsigned int)(k >> 32));
            if (ckey(x, j) >= g_rowth[i])
                out[(size_t)i * N + j] = x;
        }
    } else {
        // exact threshold, then full-column rescan for coverage
        unsigned long long cth = fallback_select<false, 128>(A, j);
        for (int i = threadIdx.x; i < N; i += 128) {
            if (i == j) continue;
            float x = A[(size_t)i * N + j];
            unsigned long long k = ckey(x, i);
            if (k >= cth && ckey(x, j) >= g_rowth[i])
                out[(size_t)i * N + j] = x;
        }
    }
}

extern "C" void kernel_launch(void* const* d_in, const int* in_sizes, int n_in,
                              void* d_out, int out_size) {
    const float* A = (const float*)d_in[0];
    float* out = (float*)d_out;
    zero_kernel<<<(N + 255) / 256, 256>>>();
    stream_kernel<<<(unsigned)(HALF / 256), 256>>>(A, out);
    rowth_kernel<<<N, 128>>>(A);
    colth_scatter_kernel<<<N, 128>>>(A, out);
}

// round 5
// speedup vs baseline: 1.3259x; 1.2051x over previous
#include <cuda_runtime.h>
#include <cstdint>

#define N     8192
#define K1    31
#define CAP   256      // global per-line candidate capacity (mean 88, max ~135)
#define RCAP  96       // per-block per-row-segment smem capacity (mean 22)
#define CCAP  224      // per-block column-candidate smem capacity (mean 44)
#define PIVOT 2.3f     // P(z>2.3)=0.0107
#define NF4   ((size_t)N * N / 4)
#define HALF  (NF4 / 2)

__device__ unsigned long long g_rowcand[(size_t)N * CAP]; // 16 MB
__device__ unsigned long long g_colcand[(size_t)N * CAP]; // 16 MB
__device__ int                g_rowcnt[N];
__device__ int                g_colcnt[N];
__device__ unsigned long long g_rowth[N];
__device__ unsigned long long g_colth[N];

// Monotone map float -> uint32 (larger float => larger key)
__device__ __forceinline__ unsigned int fkey(float x) {
    unsigned int u = __float_as_uint(x);
    return (u & 0x80000000u) ? ~u : (u | 0x80000000u);
}
__device__ __forceinline__ float inv_fkey(unsigned int k) {
    unsigned int u = (k & 0x80000000u) ? (k ^ 0x80000000u) : ~k;
    return __uint_as_float(u);
}
// Composite key: value-major, lower index wins ties (stable top_k semantics)
__device__ __forceinline__ unsigned long long ckey(float x, int idx) {
    return ((unsigned long long)fkey(x) << 32) | (unsigned int)(N - 1 - idx);
}

__global__ void zero_kernel() {
    int t = blockIdx.x * blockDim.x + threadIdx.x;
    if (t < N) { g_rowcnt[t] = 0; g_colcnt[t] = 0; }
}

// --- generic fallback: K1-th largest composite key of a full line (exact) ---
template <bool ROW>
__device__ unsigned long long fallback_select(const float* __restrict__ A, int line) {
    __shared__ unsigned long long red[128];
    unsigned long long prev = 0xFFFFFFFFFFFFFFFFull;
    for (int it = 0; it < K1; it++) {
        unsigned long long best = 0;
        for (int t = threadIdx.x; t < N; t += 128) {
            float x = ROW ? A[(size_t)line * N + t] : A[(size_t)t * N + line];
            unsigned long long k = ckey(x, t);
            if (k < prev && k > best) best = k;
        }
        red[threadIdx.x] = best;
        __syncthreads();
        for (int s = 64; s > 0; s >>= 1) {
            if (threadIdx.x < s) {
                unsigned long long o = red[threadIdx.x + s];
                if (o > red[threadIdx.x]) red[threadIdx.x] = o;
            }
            __syncthreads();
        }
        prev = red[0];
        __syncthreads();
    }
    return prev;
}

// Phase 1: streaming pass. Block covers two contiguous 2048-float segments
// (one in row b/4, one in row b/4+4096). Fully coalesced, MLP=4.
// Candidates staged in SHARED buffers; single bulk flush at block end.
__global__ __launch_bounds__(256) void stream_kernel(const float* __restrict__ A,
                                                     float* __restrict__ out) {
    const int b = blockIdx.x, t = threadIdx.x;
    const size_t base0 = (size_t)b * 512;
    const float4* Ap = (const float4*)A;
    float4* Op = (float4*)out;

    // 4 independent coalesced loads, front-batched
    float4 v0 = __ldcs(&Ap[base0 + t]);
    float4 v1 = __ldcs(&Ap[base0 + 256 + t]);
    float4 v2 = __ldcs(&Ap[base0 + HALF + t]);
    float4 v3 = __ldcs(&Ap[base0 + HALF + 256 + t]);
    const float4 zz = {0.0f, 0.0f, 0.0f, 0.0f};
    __stcs(&Op[base0 + t], zz);
    __stcs(&Op[base0 + 256 + t], zz);
    __stcs(&Op[base0 + HALF + t], zz);
    __stcs(&Op[base0 + HALF + 256 + t], zz);

    __shared__ unsigned long long rbuf[2][RCAP];
    __shared__ unsigned long long cbuf[CCAP];
    __shared__ int cjbuf[CCAP];
    __shared__ int rcnt[2];
    __shared__ int ccnt;
    __shared__ int rbase[2];
    if (t < 2) rcnt[t] = 0;
    if (t == 2) ccnt = 0;
    __syncthreads();

    const int rows[2] = {b >> 2, (b >> 2) + N / 2};
    float xs[4][4] = {{v0.x, v0.y, v0.z, v0.w}, {v1.x, v1.y, v1.z, v1.w},
                      {v2.x, v2.y, v2.z, v2.w}, {v3.x, v3.y, v3.z, v3.w}};
#pragma unroll
    for (int q = 0; q < 4; q++) {
        const int half = q >> 1;
        const int jb = (((b & 3) * 512 + ((q & 1) ? 256 + t : t)) << 2);
        const int row = rows[half];
#pragma unroll
        for (int c = 0; c < 4; c++) {
            float x = xs[q][c];
            if (x > PIVOT) {
                int j = jb + c;
                unsigned long long rk = ckey(x, j);
                int rs = atomicAdd(&rcnt[half], 1);
                if (rs < RCAP) rbuf[half][rs] = rk;
                else {  // overflow: rare direct push (still exact)
                    int gs = atomicAdd(&g_rowcnt[row], 1);
                    if (gs < CAP) g_rowcand[(size_t)row * CAP + gs] = rk;
                }
                unsigned long long ck = ckey(x, row);
                int cs = atomicAdd(&ccnt, 1);
                if (cs < CCAP) { cbuf[cs] = ck; cjbuf[cs] = j; }
                else {
                    int gs = atomicAdd(&g_colcnt[j], 1);
                    if (gs < CAP) g_colcand[(size_t)j * CAP + gs] = ck;
                }
            }
        }
    }
    __syncthreads();

    // bulk flush: one global atomic per row segment, coalesced list writes
    if (t < 2) {
        int rc = min(rcnt[t], RCAP);
        rbase[t] = rc ? atomicAdd(&g_rowcnt[rows[t]], rc) : 0;
    }
    __syncthreads();
#pragma unroll
    for (int h = 0; h < 2; h++) {
        int rc = min(rcnt[h], RCAP);
        for (int s = t; s < rc; s += 256) {
            int sl = rbase[h] + s;
            if (sl < CAP) g_rowcand[(size_t)rows[h] * CAP + sl] = rbuf[h][s];
        }
    }
    int cc = min(ccnt, CCAP);
    // ~44 independent column atomics in parallel (latency paid once per block)
    for (int s = t; s < cc; s += 256) {
        int j = cjbuf[s];
        int gs = atomicAdd(&g_colcnt[j], 1);
        if (gs < CAP) g_colcand[(size_t)j * CAP + gs] = cbuf[s];
    }
}

// Phase 2: block b computes BOTH g_rowth[b] and g_colth[b] (rank-by-counting).
__global__ __launch_bounds__(128) void thresh_kernel(const float* __restrict__ A) {
    const int line = blockIdx.x;
    __shared__ unsigned long long cand[CAP];

    // row threshold
    int c = g_rowcnt[line];
    if (c >= K1 && c <= CAP) {
        for (int t = threadIdx.x; t < c; t += 128)
            cand[t] = g_rowcand[(size_t)line * CAP + t];
        __syncthreads();
        for (int t = threadIdx.x; t < c; t += 128) {
            unsigned long long kt = cand[t];
            int r = 0;
            for (int m = 0; m < c; m++) r += (cand[m] > kt);
            if (r == K1 - 1) g_rowth[line] = kt;
        }
    } else {
        unsigned long long th = fallback_select<true>(A, line);
        if (threadIdx.x == 0) g_rowth[line] = th;
    }
    __syncthreads();

    // column threshold
    c = g_colcnt[line];
    if (c >= K1 && c <= CAP) {
        for (int t = threadIdx.x; t < c; t += 128)
            cand[t] = g_colcand[(size_t)line * CAP + t];
        __syncthreads();
        for (int t = threadIdx.x; t < c; t += 128) {
            unsigned long long kt = cand[t];
            int r = 0;
            for (int m = 0; m < c; m++) r += (cand[m] > kt);
            if (r == K1 - 1) g_colth[line] = kt;
        }
    } else {
        unsigned long long th = fallback_select<false>(A, line);
        if (threadIdx.x == 0) g_colth[line] = th;
    }
}

// Phase 3: scatter survivors from column candidate lists.
// Every entry passing both thresholds has value > PIVOT, so it is in the
// column list (unless overflow -> full-column rescan).
__global__ __launch_bounds__(128) void scatter_kernel(const float* __restrict__ A,
                                                      float* __restrict__ out) {
    const int j = blockIdx.x;
    const int c = g_colcnt[j];
    const unsigned long long cth = g_colth[j];
    if (c <= CAP) {
        for (int s = threadIdx.x; s < c; s += 128) {
            unsigned long long k = g_colcand[(size_t)j * CAP + s];
            if (k < cth) continue;
            int i = N - 1 - (int)(unsigned int)(k & 0xFFFFFFFFu);
            if (i == j) continue;
            float x = inv_fkey((unsigned int)(k >> 32));
            if (ckey(x, j) >= g_rowth[i])
                out[(size_t)i * N + j] = x;
        }
    } else {
        for (int i = threadIdx.x; i < N; i += 128) {
            if (i == j) continue;
            float x = A[(size_t)i * N + j];
            if (ckey(x, i) >= cth && ckey(x, j) >= g_rowth[i])
                out[(size_t)i * N + j] = x;
        }
    }
}

extern "C" void kernel_launch(void* const* d_in, const int* in_sizes, int n_in,
                              void* d_out, int out_size) {
    const float* A = (const float*)d_in[0];
    float* out = (float*)d_out;
    zero_kernel<<<(N + 255) / 256, 256>>>();
    stream_kernel<<<(unsigned)(HALF / 512), 256>>>(A, out);
    thresh_kernel<<<N, 128>>>(A);
    scatter_kernel<<<N, 128>>>(A, out);
}